// round 17
// baseline (speedup 1.0000x reference)
#include <cuda_runtime.h>
#include <cstdint>

#define NUM_USERS 100000
#define NUM_ITEMS 50000
#define NNODES    150000            // NUM_USERS + NUM_ITEMS
#define DIM       64
#define NEDGES    2000000

#define SCAN_NBLK     19
#define SCAN_THREADS  1024
#define SCAN_ITEMS    8
#define SCAN_CHUNK    (SCAN_THREADS * SCAN_ITEMS)   // 8192; 19*8192 >= 150000

// ---------------------------------------------------------------------------
// Scratch (__device__ globals — allocation in kernel_launch is forbidden).
// Invariants maintained across calls (graph-replay determinism):
//   g_count : all zero on entry  (module-load zero-init; scan re-zeroes)
//   g_flag  : all zero on entry  (module-load zero-init; fill re-zeroes)
// ---------------------------------------------------------------------------
__device__ float g_emb1[NNODES * DIM];   // relu(layer-1 output)
__device__ float g_acc [NNODES * DIM];   // emb0 + emb1
__device__ int   g_src [NEDGES];
__device__ int   g_dst [NEDGES];
__device__ int   g_count [NNODES];
__device__ int   g_rowptr[NNODES + 1];
__device__ int   g_cursor[NNODES];
__device__ int   g_flag  [SCAN_NBLK];
__device__ int2  g_csr[NEDGES];     // {src, __float_as_int(weight)} grouped by dst

// Virtual concat(users, items) row gather, one float4 at column t*4.
__device__ __forceinline__ float4 emb0_load(const float4* __restrict__ users,
                                            const float4* __restrict__ items,
                                            int node, int t) {
    return (node < NUM_USERS)
        ? __ldg(users + (size_t)node * 16 + t)
        : __ldg(items + (size_t)(node - NUM_USERS) * 16 + t);
}

// ---------------------------------------------------------------------------
// Launch 1: verbatim input copies + edge convert + degree count.
// Edge dtype probe: reference asks int64 but default-JAX yields int32; for
// int64 every odd 32-bit word is 0 (indices positive, < 2^31).
// Output float4 layout: users_final [0,1.6M) | users [1.6M,3.2M)
//                     | items_final [3.2M,4.0M) | items [4.0M,4.8M)
// ---------------------------------------------------------------------------
__global__ void fused_init_kernel(const int* __restrict__ ei,
                                  const float4* __restrict__ users,
                                  const float4* __restrict__ items,
                                  float4* __restrict__ out) {
    const int U4 = NUM_USERS * DIM / 4;   // 1,600,000
    const int T4 = NNODES    * DIM / 4;   // 2,400,000
    int idx = blockIdx.x * blockDim.x + threadIdx.x;

    if (idx < T4) {
        float4 v = (idx < U4) ? __ldg(users + idx) : __ldg(items + (idx - U4));
        if (idx < U4) __stcs(out + U4 + idx, v);              // emb_users copy
        else          __stcs(out + 4000000 + (idx - U4), v);  // emb_items copy
    }

    if (idx < NEDGES) {
        bool is64 = (__ldg(ei + 1) == 0) & (__ldg(ei + 3) == 0) &
                    (__ldg(ei + 5) == 0) & (__ldg(ei + 7) == 0);
        int s, d;
        if (is64) {
            int2 ps = __ldg(reinterpret_cast<const int2*>(ei) + idx);
            int2 pd = __ldg(reinterpret_cast<const int2*>(ei) + NEDGES + idx);
            s = ps.x; d = pd.x;
        } else {
            s = __ldg(ei + idx);
            d = __ldg(ei + NEDGES + idx);
        }
        g_src[idx] = s;
        g_dst[idx] = d;
        atomicAdd(&g_count[d], 1);       // g_count zero on entry (invariant)
    }
}

// ---------------------------------------------------------------------------
// Launch 2: single-kernel chained exclusive scan of g_count -> rowptr/cursor.
// 19 blocks all resident (19 << 148 SMs) so the flag chain cannot deadlock.
// Published value is prefix+1 so flag==0 means "not ready". Re-zeroes g_count.
// ---------------------------------------------------------------------------
__global__ void scan_kernel() {
    __shared__ int stot[SCAN_THREADS];
    __shared__ int s_base;
    int tid = threadIdx.x, bid = blockIdx.x;
    int base = bid * SCAN_CHUNK + tid * SCAN_ITEMS;

    int v[SCAN_ITEMS];
    int sum = 0;
    #pragma unroll
    for (int k = 0; k < SCAN_ITEMS; k++) {
        int i = base + k;
        v[k] = (i < NNODES) ? g_count[i] : 0;
        sum += v[k];
    }
    stot[tid] = sum;
    __syncthreads();
    for (int off = 1; off < SCAN_THREADS; off <<= 1) {
        int t = (tid >= off) ? stot[tid - off] : 0;
        __syncthreads();
        stot[tid] += t;
        __syncthreads();
    }
    int thr_excl = stot[tid] - sum;
    int btot = stot[SCAN_THREADS - 1];

    if (tid == 0) {
        int prev = 0;
        if (bid > 0) {
            int f;
            do { f = atomicAdd(&g_flag[bid - 1], 0); } while (f == 0);
            prev = f - 1;
        }
        atomicExch(&g_flag[bid], prev + btot + 1);
        s_base = prev;
    }
    __syncthreads();

    int off0 = s_base + thr_excl;
    #pragma unroll
    for (int k = 0; k < SCAN_ITEMS; k++) {
        int i = base + k;
        if (i < NNODES) {
            g_rowptr[i] = off0;
            g_cursor[i] = off0;
            g_count[i]  = 0;             // restore invariant for next call
        }
        off0 += v[k];
    }
    if (bid == SCAN_NBLK - 1 && tid == SCAN_THREADS - 1)
        g_rowptr[NNODES] = NEDGES;
}

// ---------------------------------------------------------------------------
// Launch 3: CSR fill (int atomics on 150K spread cursors) + flag reset.
// ---------------------------------------------------------------------------
__global__ void fill_kernel(const float* __restrict__ ew) {
    if (blockIdx.x == 0 && threadIdx.x < SCAN_NBLK)
        g_flag[threadIdx.x] = 0;         // restore invariant (scan already done)
    int e = blockIdx.x * blockDim.x + threadIdx.x;
    if (e >= NEDGES) return;
    int d = g_dst[e];
    int slot = atomicAdd(&g_cursor[d], 1);
    g_csr[slot] = make_int2(g_src[e], __float_as_int(__ldg(ew + e)));
}

// ---------------------------------------------------------------------------
// Gather-reduce over a node's CSR range. 16 threads/node, one float4 each.
// Gather source is either the virtual input concat (layer 1) or g_emb1.
// ---------------------------------------------------------------------------
template <int LAYER1>
__device__ __forceinline__ float4 gather_reduce(int node, int t,
                                                const float4* __restrict__ users,
                                                const float4* __restrict__ items) {
    int beg = __ldg(&g_rowptr[node]);
    int end = __ldg(&g_rowptr[node + 1]);

    float4 s = make_float4(0.f, 0.f, 0.f, 0.f);
    int i = beg;
    for (; i + 3 < end; i += 4) {
        int2 p0 = __ldg(&g_csr[i + 0]);
        int2 p1 = __ldg(&g_csr[i + 1]);
        int2 p2 = __ldg(&g_csr[i + 2]);
        int2 p3 = __ldg(&g_csr[i + 3]);
        float4 v0, v1, v2, v3;
        if (LAYER1) {
            v0 = emb0_load(users, items, p0.x, t);
            v1 = emb0_load(users, items, p1.x, t);
            v2 = emb0_load(users, items, p2.x, t);
            v3 = emb0_load(users, items, p3.x, t);
        } else {
            v0 = __ldg(reinterpret_cast<const float4*>(g_emb1) + (size_t)p0.x * 16 + t);
            v1 = __ldg(reinterpret_cast<const float4*>(g_emb1) + (size_t)p1.x * 16 + t);
            v2 = __ldg(reinterpret_cast<const float4*>(g_emb1) + (size_t)p2.x * 16 + t);
            v3 = __ldg(reinterpret_cast<const float4*>(g_emb1) + (size_t)p3.x * 16 + t);
        }
        float w0 = __int_as_float(p0.y), w1 = __int_as_float(p1.y);
        float w2 = __int_as_float(p2.y), w3 = __int_as_float(p3.y);
        s.x = fmaf(w0, v0.x, s.x); s.y = fmaf(w0, v0.y, s.y);
        s.z = fmaf(w0, v0.z, s.z); s.w = fmaf(w0, v0.w, s.w);
        s.x = fmaf(w1, v1.x, s.x); s.y = fmaf(w1, v1.y, s.y);
        s.z = fmaf(w1, v1.z, s.z); s.w = fmaf(w1, v1.w, s.w);
        s.x = fmaf(w2, v2.x, s.x); s.y = fmaf(w2, v2.y, s.y);
        s.z = fmaf(w2, v2.z, s.z); s.w = fmaf(w2, v2.w, s.w);
        s.x = fmaf(w3, v3.x, s.x); s.y = fmaf(w3, v3.y, s.y);
        s.z = fmaf(w3, v3.z, s.z); s.w = fmaf(w3, v3.w, s.w);
    }
    for (; i < end; i++) {
        int2 p = __ldg(&g_csr[i]);
        float4 v = LAYER1 ? emb0_load(users, items, p.x, t)
                          : __ldg(reinterpret_cast<const float4*>(g_emb1) + (size_t)p.x * 16 + t);
        float w = __int_as_float(p.y);
        s.x = fmaf(w, v.x, s.x); s.y = fmaf(w, v.y, s.y);
        s.z = fmaf(w, v.z, s.z); s.w = fmaf(w, v.w, s.w);
    }
    s.x = fmaxf(s.x, 0.f); s.y = fmaxf(s.y, 0.f);
    s.z = fmaxf(s.z, 0.f); s.w = fmaxf(s.w, 0.f);
    return s;
}

// ---------------------------------------------------------------------------
// Launch 4: layer-1 SpMM. Gathers straight from the input buffers, writes
// emb1 = relu(A@emb0) and acc = emb0 + emb1 (emb0 row read on the fly).
// ---------------------------------------------------------------------------
__global__ void spmm1_kernel(const float4* __restrict__ users,
                             const float4* __restrict__ items) {
    unsigned gid = blockIdx.x * blockDim.x + threadIdx.x;
    int node = gid >> 4;
    if (node >= NNODES) return;
    int t = gid & 15;

    float4 s = gather_reduce<1>(node, t, users, items);

    size_t o = (size_t)node * 16 + t;
    reinterpret_cast<float4*>(g_emb1)[o] = s;
    float4 e0 = emb0_load(users, items, node, t);
    s.x += e0.x; s.y += e0.y; s.z += e0.z; s.w += e0.w;
    reinterpret_cast<float4*>(g_acc)[o] = s;    // emb0 + emb1
}

// ---------------------------------------------------------------------------
// Launch 5: layer-2 SpMM fused with the final linear layer.
// Block = 256 threads = 16 nodes. After the gather-reduce, stage
// r = (acc + relu(s)) / 3 in shared and multiply by shared-resident W^T,
// writing the output rows directly. emb2 is never materialized.
// ---------------------------------------------------------------------------
__global__ void __launch_bounds__(256)
spmm2_final_kernel(const float* __restrict__ W,
                   const float* __restrict__ b,
                   float* __restrict__ out) {
    __shared__ float Wt[DIM * DIM];     // Wt[k][j] = W[j][k]
    __shared__ float bs[DIM];
    __shared__ float rows[16][DIM];

    int tid = threadIdx.x;
    for (int i = tid; i < DIM * DIM; i += 256) {
        int j = i >> 6, k = i & 63;
        Wt[k * DIM + j] = __ldg(W + i);
    }
    if (tid < DIM) bs[tid] = __ldg(b + tid);

    int g = tid >> 4;                   // node within block (0..15)
    int t = tid & 15;                   // float4 column within row
    int node = blockIdx.x * 16 + g;

    float4 s = gather_reduce<0>(node, t, nullptr, nullptr);

    size_t o = (size_t)node * 16 + t;
    float4 a = __ldg(reinterpret_cast<const float4*>(g_acc) + o);
    const float inv3 = 1.0f / 3.0f;
    rows[g][t * 4 + 0] = (a.x + s.x) * inv3;
    rows[g][t * 4 + 1] = (a.y + s.y) * inv3;
    rows[g][t * 4 + 2] = (a.z + s.z) * inv3;
    rows[g][t * 4 + 3] = (a.w + s.w) * inv3;
    __syncthreads();

    // Each thread computes out[node][4t .. 4t+3].
    int j0 = t * 4;
    float4 acc4 = make_float4(bs[j0], bs[j0 + 1], bs[j0 + 2], bs[j0 + 3]);
    #pragma unroll
    for (int k = 0; k < DIM; k++) {
        float rk = rows[g][k];                          // broadcast
        float4 wk = *reinterpret_cast<const float4*>(&Wt[k * DIM + j0]);
        acc4.x = fmaf(rk, wk.x, acc4.x);
        acc4.y = fmaf(rk, wk.y, acc4.y);
        acc4.z = fmaf(rk, wk.z, acc4.z);
        acc4.w = fmaf(rk, wk.w, acc4.w);
    }

    // users_final rows at [0,100000); items_final rows shifted past the
    // emb_users verbatim copy.
    size_t off4 = (node < NUM_USERS) ? (size_t)node * 16 + t
                                     : (size_t)(node + NUM_USERS) * 16 + t;
    __stcs(reinterpret_cast<float4*>(out) + off4, acc4);
}

// ---------------------------------------------------------------------------
// Launch. Inputs (metadata order): edge_index (2,E), edge_weight (E,) f32,
// emb_users (100000,64) f32, emb_items (50000,64) f32, W (64,64), b (64,).
// 5 launches total.
// ---------------------------------------------------------------------------
extern "C" void kernel_launch(void* const* d_in, const int* in_sizes, int n_in,
                              void* d_out, int out_size) {
    const int*   ei    = (const int*)  d_in[0];
    const float* ew    = (const float*)d_in[1];
    const float* users = (const float*)d_in[2];
    const float* items = (const float*)d_in[3];
    const float* W     = (const float*)d_in[4];
    const float* b     = (const float*)d_in[5];
    float*       out   = (float*)d_out;

    const int T4 = NNODES * DIM / 4;                       // 2.4M (covers NEDGES too)

    fused_init_kernel<<<(T4 + 255) / 256, 256>>>(
        ei, (const float4*)users, (const float4*)items, (float4*)out); // 1
    scan_kernel<<<SCAN_NBLK, SCAN_THREADS>>>();                        // 2
    fill_kernel<<<(NEDGES + 255) / 256, 256>>>(ew);                    // 3
    spmm1_kernel<<<(NNODES * 16 + 255) / 256, 256>>>(
        (const float4*)users, (const float4*)items);                  // 4 (profiled)
    spmm2_final_kernel<<<NNODES / 16, 256>>>(W, b, out);               // 5
}